// round 1
// baseline (speedup 1.0000x reference)
#include <cuda_runtime.h>

#define N 8192
#define D 128
#define MARGIN 0.3f
#define BI 64
#define BJ 256
#define FINF __int_as_float(0x7f800000)

__device__ float g_sq[N];
__device__ int   g_tgt[N];
__device__ float g_hinge[N];
__device__ int   g_is64;

// ---------------------------------------------------------------------------
// Kernel 0: detect whether targets buffer is int64 or int32.
// For int64 (values in [0,256)), every odd 32-bit word is 0.
// For int32 random targets, odd words are random values < 256 (not all zero).
// ---------------------------------------------------------------------------
__global__ void detect_kernel(const unsigned int* __restrict__ t) {
    __shared__ unsigned int sred[256];
    unsigned int acc = 0;
    for (int i = threadIdx.x; i < N / 2; i += 256) acc |= t[2 * i + 1];
    sred[threadIdx.x] = acc;
    __syncthreads();
    for (int s = 128; s > 0; s >>= 1) {
        if (threadIdx.x < s) sred[threadIdx.x] |= sred[threadIdx.x + s];
        __syncthreads();
    }
    if (threadIdx.x == 0) g_is64 = (sred[0] == 0u) ? 1 : 0;
}

// ---------------------------------------------------------------------------
// Kernel 1: per-row squared norms + target conversion to int32.
// ---------------------------------------------------------------------------
__global__ void prep_kernel(const float* __restrict__ x, const void* __restrict__ tgt) {
    int i = blockIdx.x;
    int t = threadIdx.x;  // 128 threads, one per k
    float v = x[i * D + t];
    v *= v;
    #pragma unroll
    for (int o = 16; o > 0; o >>= 1) v += __shfl_xor_sync(0xffffffffu, v, o);
    __shared__ float ws[4];
    if ((t & 31) == 0) ws[t >> 5] = v;
    __syncthreads();
    if (t == 0) {
        g_sq[i] = ws[0] + ws[1] + ws[2] + ws[3];
        if (g_is64) g_tgt[i] = (int)((const long long*)tgt)[i];
        else        g_tgt[i] = ((const int*)tgt)[i];
    }
}

// ---------------------------------------------------------------------------
// Kernel 2: fused pairwise-distance GEMM + per-row triplet statistics.
// Each block: 64 rows x full 8192-j sweep. 256 threads, 8x8 register tile.
// SMEM tiles stored K-major with XOR swizzle col ^= (k>>2)&31:
//   - float4 global loads -> 4 scalar STS, conflict-free
//   - strided scalar LDS reads in mainloop, conflict-free
// ---------------------------------------------------------------------------
__global__ void __launch_bounds__(256, 1)
main_kernel(const float* __restrict__ x) {
    extern __shared__ float smem[];
    float* As = smem;             // [128][64]
    float* Bs = smem + D * BI;    // [128][256]

    int tid  = threadIdx.x;
    int lane = tid & 31;
    int wid  = tid >> 5;          // warp id 0..7: warp owns rows wid*8..wid*8+7
    int i0   = blockIdx.x * BI;

    const float4* X4 = (const float4*)x;

    // Load A tile (64 rows x 128 k), swizzled K-major.
    for (int idx = tid; idx < BI * 32; idx += 256) {
        int i  = idx >> 5;
        int kq = idx & 31;
        float4 v = X4[(i0 + i) * 32 + kq];
        int col = i ^ kq;                 // swizzle: s(k) = (k>>2)&31 = kq
        As[(4 * kq + 0) * BI + col] = v.x;
        As[(4 * kq + 1) * BI + col] = v.y;
        As[(4 * kq + 2) * BI + col] = v.z;
        As[(4 * kq + 3) * BI + col] = v.w;
    }

    // Per-warp row metadata (all lanes keep all 8 rows).
    int rbase = i0 + wid * 8;
    float sq_i[8];
    int   tg_i[8];
    #pragma unroll
    for (int r = 0; r < 8; r++) {
        sq_i[r] = g_sq[rbase + r];
        tg_i[r] = g_tgt[rbase + r];
    }

    // Running per-row stats, owned by lane L for row rbase+L (lanes 0..7).
    float S_ps = 0.0f, S_ns = 0.0f;
    float S_pmin = FINF, S_pmax = -FINF, S_pmax2 = -FINF, S_nmin = FINF;
    int   S_pc = 0, S_pmi = -1, S_pma = -1;

    for (int jt = 0; jt < N; jt += BJ) {
        __syncthreads();  // previous iteration's readers done with Bs

        // Load B tile (256 rows x 128 k), swizzled K-major.
        for (int idx = tid; idx < BJ * 32; idx += 256) {
            int j  = idx >> 5;
            int kq = idx & 31;
            float4 v = X4[(jt + j) * 32 + kq];
            int col = j ^ kq;
            Bs[(4 * kq + 0) * BJ + col] = v.x;
            Bs[(4 * kq + 1) * BJ + col] = v.y;
            Bs[(4 * kq + 2) * BJ + col] = v.z;
            Bs[(4 * kq + 3) * BJ + col] = v.w;
        }
        __syncthreads();

        float acc[8][8];
        #pragma unroll
        for (int r = 0; r < 8; r++)
            #pragma unroll
            for (int c = 0; c < 8; c++) acc[r][c] = 0.0f;

        for (int kq = 0; kq < 32; kq++) {
            int xk = lane ^ kq;
            #pragma unroll
            for (int c4 = 0; c4 < 4; c4++) {
                int k = 4 * kq + c4;
                const float* ar = As + k * BI;
                const float* br = Bs + k * BJ;
                float a[8], b[8];
                #pragma unroll
                for (int r = 0; r < 8; r++) a[r] = ar[(wid * 8 + r) ^ kq];
                #pragma unroll
                for (int c = 0; c < 8; c++) b[c] = br[c * 32 + xk];
                #pragma unroll
                for (int r = 0; r < 8; r++)
                    #pragma unroll
                    for (int c = 0; c < 8; c++)
                        acc[r][c] = fmaf(a[r], b[c], acc[r][c]);
            }
        }

        // Epilogue: this thread holds cols j = jt + lane + 32*c, c=0..7.
        float sq_j[8];
        int   tg_j[8];
        #pragma unroll
        for (int c = 0; c < 8; c++) {
            int j = jt + lane + 32 * c;
            sq_j[c] = g_sq[j];
            tg_j[c] = g_tgt[j];
        }

        #pragma unroll
        for (int r = 0; r < 8; r++) {
            float ps = 0.0f, ns = 0.0f;
            float pmin = FINF, pmax = -FINF, pmax2 = -FINF, nmin = FINF;
            int pc = 0, pmi = -1, pma = -1;
            #pragma unroll
            for (int c = 0; c < 8; c++) {
                int j = jt + lane + 32 * c;
                float d2  = sq_i[r] + sq_j[c] - 2.0f * acc[r][c];
                float dsq = fmaxf(d2, 1e-12f);
                if (tg_i[r] == tg_j[c]) {
                    ps += dsq;
                    pc++;
                    if (dsq < pmin) { pmin = dsq; pmi = j; }
                    if (dsq > pmax) { pmax2 = pmax; pmax = dsq; pma = j; }
                    else if (dsq > pmax2) pmax2 = dsq;
                } else {
                    ns += dsq;
                    nmin = fminf(nmin, dsq);
                }
            }
            // Butterfly reduction across the 32 lanes (all lanes converge).
            #pragma unroll
            for (int o = 16; o > 0; o >>= 1) {
                ps += __shfl_xor_sync(0xffffffffu, ps, o);
                pc += __shfl_xor_sync(0xffffffffu, pc, o);
                ns += __shfl_xor_sync(0xffffffffu, ns, o);
                nmin = fminf(nmin, __shfl_xor_sync(0xffffffffu, nmin, o));

                float omin = __shfl_xor_sync(0xffffffffu, pmin, o);
                int   omi  = __shfl_xor_sync(0xffffffffu, pmi, o);
                if (omin < pmin || (omin == pmin && (unsigned)omi < (unsigned)pmi)) {
                    pmin = omin; pmi = omi;
                }

                float omax  = __shfl_xor_sync(0xffffffffu, pmax, o);
                float omax2 = __shfl_xor_sync(0xffffffffu, pmax2, o);
                int   oma   = __shfl_xor_sync(0xffffffffu, pma, o);
                if (omax > pmax)      { pmax2 = fmaxf(pmax, omax2); pmax = omax; pma = oma; }
                else if (omax < pmax) { pmax2 = fmaxf(pmax2, omax); }
                else {
                    if (pma >= 0) pmax2 = pmax;            // equal finite maxima
                    pma = min(pma, oma);
                    pmax2 = fmaxf(pmax2, omax2);
                }
            }
            if (lane == r) {
                S_ps += ps; S_pc += pc; S_ns += ns;
                S_nmin = fminf(S_nmin, nmin);
                if (pmin < S_pmin || (pmin == S_pmin && (unsigned)pmi < (unsigned)S_pmi)) {
                    S_pmin = pmin; S_pmi = pmi;
                }
                if (pmax > S_pmax)      { S_pmax2 = fmaxf(S_pmax, pmax2); S_pmax = pmax; S_pma = pma; }
                else if (pmax < S_pmax) { S_pmax2 = fmaxf(S_pmax2, pmax); }
                else {
                    if (S_pma >= 0) S_pmax2 = S_pmax;
                    S_pma = min(S_pma, pma);
                    S_pmax2 = fmaxf(S_pmax2, pmax2);
                }
            }
        }
    }

    // Finalize this warp's 8 rows (lane L owns row rbase+L).
    if (lane < 8) {
        float cntp = (float)(S_pc - 1);                 // drop argmin (self)
        float sp   = (S_ps - S_pmin) / cntp;
        float mp   = (S_pma == S_pmi) ? S_pmax2 : S_pmax;
        float ap   = mp / sp + 0.5f * logf(sp);
        float cntn = (float)(N - S_pc);
        float sn   = S_ns / cntn;
        float an   = S_nmin / sn + 0.5f * logf(sn);
        g_hinge[rbase + lane] = fmaxf(ap - an + MARGIN, 0.0f);
    }
}

// ---------------------------------------------------------------------------
// Kernel 3: deterministic mean of hinges -> scalar loss.
// ---------------------------------------------------------------------------
__global__ void finalize_kernel(float* __restrict__ out) {
    __shared__ float sm[256];
    float s = 0.0f;
    for (int i = threadIdx.x; i < N; i += 256) s += g_hinge[i];
    sm[threadIdx.x] = s;
    __syncthreads();
    for (int o = 128; o > 0; o >>= 1) {
        if (threadIdx.x < o) sm[threadIdx.x] += sm[threadIdx.x + o];
        __syncthreads();
    }
    if (threadIdx.x == 0) out[0] = sm[0] / (float)N;
}

extern "C" void kernel_launch(void* const* d_in, const int* in_sizes, int n_in,
                              void* d_out, int out_size) {
    (void)in_sizes; (void)n_in; (void)out_size;
    const float* x   = (const float*)d_in[0];
    const void*  tgt = d_in[1];

    detect_kernel<<<1, 256>>>((const unsigned int*)tgt);
    prep_kernel<<<N, 128>>>(x, tgt);

    int smem_bytes = (D * BI + D * BJ) * (int)sizeof(float);  // 163840
    cudaFuncSetAttribute(main_kernel, cudaFuncAttributeMaxDynamicSharedMemorySize, smem_bytes);
    main_kernel<<<N / BI, 256, smem_bytes>>>(x);

    finalize_kernel<<<1, 256>>>((float*)d_out);
}

// round 2
// speedup vs baseline: 1.2630x; 1.2630x over previous
#include <cuda_runtime.h>

#define N 8192
#define D 128
#define MARGIN 0.3f
#define BI 64
#define BJ 256
#define FINF __int_as_float(0x7f800000)
#define NCLS 256

__device__ float g_sq[N];
__device__ int   g_tgt[N];
__device__ int   g_cc[NCLS];
__device__ float g_hinge[N];
__device__ int   g_is64;

// packed dual-FMA: d = a*b + d  (two fp32 lanes per instruction)
#define FMA2(d, a, b) \
    asm("fma.rn.f32x2 %0, %1, %2, %0;" : "+l"(d) : "l"(a), "l"(b))
#define UNPK2(lo, hi, v) \
    asm("mov.b64 {%0,%1}, %2;" : "=f"(lo), "=f"(hi) : "l"(v))

// ---------------------------------------------------------------------------
// Kernel 0: int64-vs-int32 detection for targets + zero the class histogram.
// ---------------------------------------------------------------------------
__global__ void detect_kernel(const unsigned int* __restrict__ t) {
    __shared__ unsigned int sred[256];
    unsigned int acc = 0;
    for (int i = threadIdx.x; i < N / 2; i += 256) acc |= t[2 * i + 1];
    sred[threadIdx.x] = acc;
    __syncthreads();
    for (int s = 128; s > 0; s >>= 1) {
        if (threadIdx.x < s) sred[threadIdx.x] |= sred[threadIdx.x + s];
        __syncthreads();
    }
    if (threadIdx.x == 0) g_is64 = (sred[0] == 0u) ? 1 : 0;
    if (threadIdx.x < NCLS) g_cc[threadIdx.x] = 0;
}

// ---------------------------------------------------------------------------
// Kernel 1: per-row squared norms, target conversion, class histogram.
// ---------------------------------------------------------------------------
__global__ void prep_kernel(const float* __restrict__ x, const void* __restrict__ tgt) {
    int i = blockIdx.x;
    int t = threadIdx.x;  // 128 threads, one per k
    float v = x[i * D + t];
    v *= v;
    #pragma unroll
    for (int o = 16; o > 0; o >>= 1) v += __shfl_xor_sync(0xffffffffu, v, o);
    __shared__ float ws[4];
    if ((t & 31) == 0) ws[t >> 5] = v;
    __syncthreads();
    if (t == 0) {
        g_sq[i] = ws[0] + ws[1] + ws[2] + ws[3];
        int tg;
        if (g_is64) tg = (int)((const long long*)tgt)[i];
        else        tg = ((const int*)tgt)[i];
        g_tgt[i] = tg;
        atomicAdd(&g_cc[tg], 1);
    }
}

// ---------------------------------------------------------------------------
// Kernel 2: fused pairwise-distance GEMM (packed f32x2 FMA) + stats.
// Block: 64 rows x full 8192-j sweep. 256 threads, 8 rows x 4 col-pairs each.
// A tile stored DUPLICATED (a,a) as float2 -> LDS.64 broadcast = packed operand.
// B tile pair-swizzled: col j at 2*((j>>1)^(k>>2)) + (j&1) -> conflict-free
//   LDS.64 pair reads in the mainloop.
// Per-thread register accumulation of (sum_pos, max_pos, sum_neg, min_neg)
// per row across ALL tiles; single butterfly reduction at the end.
// Self-distance (j==i) skipped: it is the argmin positive the reference drops.
// ---------------------------------------------------------------------------
__global__ void __launch_bounds__(256, 1)
main_kernel(const float* __restrict__ x) {
    extern __shared__ char smem_raw[];
    float2* As2 = (float2*)smem_raw;                            // [128][64] dup
    float*  Bs  = (float*)(smem_raw + 65536);                   // [128][256]
    float*  sqs = (float*)(smem_raw + 65536 + 131072);          // [256]
    int*    tgs = (int*)  (smem_raw + 65536 + 131072 + 1024);   // [256]

    int tid  = threadIdx.x;
    int lane = tid & 31;
    int wid  = tid >> 5;
    int i0   = blockIdx.x * BI;

    const float4* X4 = (const float4*)x;

    // A tile: 64 rows x 128 k, duplicated, swizzled (col = i ^ kq).
    for (int idx = tid; idx < BI * 32; idx += 256) {
        int i  = idx >> 5;
        int kq = idx & 31;
        float4 v = X4[(i0 + i) * 32 + kq];
        int col = i ^ kq;
        As2[(4 * kq + 0) * BI + col] = make_float2(v.x, v.x);
        As2[(4 * kq + 1) * BI + col] = make_float2(v.y, v.y);
        As2[(4 * kq + 2) * BI + col] = make_float2(v.z, v.z);
        As2[(4 * kq + 3) * BI + col] = make_float2(v.w, v.w);
    }

    int rbase = i0 + wid * 8;
    float sq_i[8];
    int   tg_i[8];
    #pragma unroll
    for (int r = 0; r < 8; r++) {
        sq_i[r] = g_sq[rbase + r];
        tg_i[r] = g_tgt[rbase + r];
    }

    float ps[8], pmax[8], ns[8], nmin[8];
    #pragma unroll
    for (int r = 0; r < 8; r++) {
        ps[r] = 0.0f; ns[r] = 0.0f; pmax[r] = -FINF; nmin[r] = FINF;
    }

    for (int jt = 0; jt < N; jt += BJ) {
        __syncthreads();  // previous iteration's readers done with Bs

        // B tile: 256 rows x 128 k, pair-swizzled.
        for (int idx = tid; idx < BJ * 32; idx += 256) {
            int j  = idx >> 5;
            int kq = idx & 31;
            float4 v = X4[(jt + j) * 32 + kq];
            int p2 = 2 * ((j >> 1) ^ kq) + (j & 1);
            Bs[(4 * kq + 0) * BJ + p2] = v.x;
            Bs[(4 * kq + 1) * BJ + p2] = v.y;
            Bs[(4 * kq + 2) * BJ + p2] = v.z;
            Bs[(4 * kq + 3) * BJ + p2] = v.w;
        }
        sqs[tid] = g_sq[jt + tid];
        tgs[tid] = g_tgt[jt + tid];
        __syncthreads();

        unsigned long long acc2[8][4];
        #pragma unroll
        for (int r = 0; r < 8; r++)
            #pragma unroll
            for (int c = 0; c < 4; c++) acc2[r][c] = 0ull;

        for (int kq = 0; kq < 32; kq++) {
            #pragma unroll
            for (int c4 = 0; c4 < 4; c4++) {
                int k = 4 * kq + c4;
                const unsigned long long* ar =
                    (const unsigned long long*)(As2 + k * BI);
                const float* br = Bs + k * BJ;
                unsigned long long a2[8], b2[4];
                #pragma unroll
                for (int r = 0; r < 8; r++) a2[r] = ar[(wid * 8 + r) ^ kq];
                #pragma unroll
                for (int c = 0; c < 4; c++)
                    b2[c] = *(const unsigned long long*)(br + 2 * (lane ^ kq) + 64 * c);
                #pragma unroll
                for (int r = 0; r < 8; r++)
                    #pragma unroll
                    for (int c = 0; c < 4; c++)
                        FMA2(acc2[r][c], a2[r], b2[c]);
            }
        }

        // Epilogue: thread owns columns j = jt + 2*lane + 64*c + {0,1}.
        float sqj[8];
        int   tgj[8];
        #pragma unroll
        for (int c = 0; c < 4; c++) {
            int jl = 2 * lane + 64 * c;
            sqj[2 * c]     = sqs[jl];
            sqj[2 * c + 1] = sqs[jl + 1];
            tgj[2 * c]     = tgs[jl];
            tgj[2 * c + 1] = tgs[jl + 1];
        }

        #pragma unroll
        for (int r = 0; r < 8; r++) {
            int irow = rbase + r;
            #pragma unroll
            for (int c = 0; c < 4; c++) {
                float lo, hi;
                UNPK2(lo, hi, acc2[r][c]);
                int j0 = jt + 2 * lane + 64 * c;

                float d0 = fmaxf(fmaf(-2.0f, lo, sq_i[r] + sqj[2 * c]), 1e-12f);
                if (tg_i[r] == tgj[2 * c]) {
                    if (j0 != irow) { ps[r] += d0; pmax[r] = fmaxf(pmax[r], d0); }
                } else {
                    ns[r] += d0; nmin[r] = fminf(nmin[r], d0);
                }

                float d1 = fmaxf(fmaf(-2.0f, hi, sq_i[r] + sqj[2 * c + 1]), 1e-12f);
                if (tg_i[r] == tgj[2 * c + 1]) {
                    if (j0 + 1 != irow) { ps[r] += d1; pmax[r] = fmaxf(pmax[r], d1); }
                } else {
                    ns[r] += d1; nmin[r] = fminf(nmin[r], d1);
                }
            }
        }
    }

    // One butterfly reduction per row; lane r finalizes row rbase+r.
    #pragma unroll
    for (int r = 0; r < 8; r++) {
        float a = ps[r], b = pmax[r], c = ns[r], d = nmin[r];
        #pragma unroll
        for (int o = 16; o > 0; o >>= 1) {
            a += __shfl_xor_sync(0xffffffffu, a, o);
            b = fmaxf(b, __shfl_xor_sync(0xffffffffu, b, o));
            c += __shfl_xor_sync(0xffffffffu, c, o);
            d = fminf(d, __shfl_xor_sync(0xffffffffu, d, o));
        }
        if (lane == r) {
            int   cc   = g_cc[tg_i[r]];
            float cntp = (float)(cc - 1);
            float sp   = a / cntp;
            float ap   = b / sp + 0.5f * logf(sp);
            float cntn = (float)(N - cc);
            float sn   = c / cntn;
            float an   = d / sn + 0.5f * logf(sn);
            g_hinge[rbase + r] = fmaxf(ap - an + MARGIN, 0.0f);
        }
    }
}

// ---------------------------------------------------------------------------
// Kernel 3: deterministic mean of hinges -> scalar loss.
// ---------------------------------------------------------------------------
__global__ void finalize_kernel(float* __restrict__ out) {
    __shared__ float sm[256];
    float s = 0.0f;
    for (int i = threadIdx.x; i < N; i += 256) s += g_hinge[i];
    sm[threadIdx.x] = s;
    __syncthreads();
    for (int o = 128; o > 0; o >>= 1) {
        if (threadIdx.x < o) sm[threadIdx.x] += sm[threadIdx.x + o];
        __syncthreads();
    }
    if (threadIdx.x == 0) out[0] = sm[0] / (float)N;
}

extern "C" void kernel_launch(void* const* d_in, const int* in_sizes, int n_in,
                              void* d_out, int out_size) {
    (void)in_sizes; (void)n_in; (void)out_size;
    const float* x   = (const float*)d_in[0];
    const void*  tgt = d_in[1];

    detect_kernel<<<1, 256>>>((const unsigned int*)tgt);
    prep_kernel<<<N, 128>>>(x, tgt);

    int smem_bytes = 65536 + 131072 + 1024 + 1024;  // 198656
    cudaFuncSetAttribute(main_kernel, cudaFuncAttributeMaxDynamicSharedMemorySize, smem_bytes);
    main_kernel<<<N / BI, 256, smem_bytes>>>(x);

    finalize_kernel<<<1, 256>>>((float*)d_out);
}

// round 5
// speedup vs baseline: 3.5479x; 2.8090x over previous
#include <cuda_runtime.h>
#include <cuda_bf16.h>
#include <cstdint>

#define N 8192
#define D 128
#define MARGIN 0.3f
#define NCLS 256
#define FINF __int_as_float(0x7f800000)

__device__ __nv_bfloat16 g_x0[N * D];   // hi bf16 split
__device__ __nv_bfloat16 g_x1[N * D];   // lo bf16 split
__device__ float2        g_sqtg[N];     // (sq_norm, target-as-bits)
__device__ int           g_cc[NCLS];
__device__ int           g_is64;
__device__ float4        g_part[4 * N]; // per (half, wc) partial stats

// ---------------- PTX helpers ----------------
__device__ __forceinline__ uint32_t smem_u32(const void* p) {
    uint32_t a;
    asm("{ .reg .u64 t; cvta.to.shared.u64 t, %1; cvt.u32.u64 %0, t; }"
        : "=r"(a) : "l"(p));
    return a;
}
#define CP16(dst, src) \
    asm volatile("cp.async.cg.shared.global [%0], [%1], 16;" \
        :: "r"(dst), "l"(src) : "memory")
#define CP_COMMIT() asm volatile("cp.async.commit_group;" ::: "memory")
#define CP_WAIT(n)  asm volatile("cp.async.wait_group %0;" :: "n"(n) : "memory")

#define LDSM4(r, a) \
    asm volatile("ldmatrix.sync.aligned.m8n8.x4.shared.b16 {%0,%1,%2,%3}, [%4];" \
        : "=r"((r)[0]), "=r"((r)[1]), "=r"((r)[2]), "=r"((r)[3]) : "r"(a))

#define MMA(c, a, b0_, b1_) \
    asm volatile("mma.sync.aligned.m16n8k16.row.col.f32.bf16.bf16.f32 " \
        "{%0,%1,%2,%3},{%4,%5,%6,%7},{%8,%9},{%0,%1,%2,%3};" \
        : "+f"((c)[0]), "+f"((c)[1]), "+f"((c)[2]), "+f"((c)[3]) \
        : "r"((a)[0]), "r"((a)[1]), "r"((a)[2]), "r"((a)[3]), "r"(b0_), "r"(b1_))

// SMEM layout (64KB A, 2x64KB B, 1KB stage)
#define OFF_A     0
#define OFF_B0    65536
#define OFF_B1    131072
#define OFF_STAGE 196608
#define SMEM_REQ  (196608 + 1024)

// ---------------------------------------------------------------------------
__global__ void detect_kernel(const unsigned int* __restrict__ t) {
    __shared__ unsigned int sred[256];
    unsigned int acc = 0;
    for (int i = threadIdx.x; i < N / 2; i += 256) acc |= t[2 * i + 1];
    sred[threadIdx.x] = acc;
    __syncthreads();
    for (int s = 128; s > 0; s >>= 1) {
        if (threadIdx.x < s) sred[threadIdx.x] |= sred[threadIdx.x + s];
        __syncthreads();
    }
    if (threadIdx.x == 0) g_is64 = (sred[0] == 0u) ? 1 : 0;
    if (threadIdx.x < NCLS) g_cc[threadIdx.x] = 0;
}

// bf16 split + norms + targets + class histogram
__global__ void prep_kernel(const float* __restrict__ x, const void* __restrict__ tgt) {
    int i = blockIdx.x;
    int t = threadIdx.x;  // 128 threads = one k each
    float v = x[i * D + t];
    __nv_bfloat16 b0 = __float2bfloat16(v);
    float lo = v - __bfloat162float(b0);
    g_x0[i * D + t] = b0;
    g_x1[i * D + t] = __float2bfloat16(lo);
    float s = v * v;
    #pragma unroll
    for (int o = 16; o > 0; o >>= 1) s += __shfl_xor_sync(0xffffffffu, s, o);
    __shared__ float ws[4];
    if ((t & 31) == 0) ws[t >> 5] = s;
    __syncthreads();
    if (t == 0) {
        int tg;
        if (g_is64) tg = (int)((const long long*)tgt)[i];
        else        tg = ((const int*)tgt)[i];
        g_sqtg[i] = make_float2(ws[0] + ws[1] + ws[2] + ws[3], __int_as_float(tg));
        atomicAdd(&g_cc[tg], 1);
    }
}

// ---------------------------------------------------------------------------
// Main: mma.sync bf16-split distance GEMM + fused per-row stats.
// Grid 128 = 64 row-tiles x 2 j-halves. 8 warps (4 row-groups x 2 col-groups),
// warp tile 32x64. Double-buffered cp.async B chunks (128 cols each).
// Tile layout per split s, k-half h: [s*32KB + h*16KB + row*128B], with
// per-row XOR swizzle (w ^ ((row&7)<<4)) == SW128 within each 1KB atom.
// ---------------------------------------------------------------------------
__global__ void __launch_bounds__(256, 1) main_kernel() {
    extern __shared__ __align__(1024) char smraw[];
    uint32_t sb = smem_u32(smraw);
    float2* stage = (float2*)(smraw + OFF_STAGE);

    int tid  = threadIdx.x;
    int lane = tid & 31;
    int wid  = tid >> 5;
    int wr   = wid >> 1;          // row group (32 rows)
    int wc   = wid & 1;           // col group (64 cols)
    int i0   = (blockIdx.x >> 1) * 128;
    int half = blockIdx.x & 1;
    int jb   = half * 4096;

    // ---- A tile via cp.async (rows i0..i0+127, both splits) ----
    #pragma unroll
    for (int t = 0; t < 16; t++) {
        int idx = tid + t * 256;           // 0..4095 16B chunks
        int s   = idx >> 11;
        int rem = idx & 2047;
        int r   = rem >> 4;
        int kc  = rem & 15;
        const __nv_bfloat16* src = (s ? g_x1 : g_x0) + (i0 + r) * D + kc * 8;
        uint32_t dst = sb + OFF_A + s * 32768 + (kc >> 3) * 16384 + r * 128
                     + (((kc & 7) << 4) ^ ((r & 7) << 4));
        CP16(dst, src);
    }
    CP_COMMIT();

    // ---- B chunk 0 ----
    {
        int j0 = jb;
        #pragma unroll
        for (int t = 0; t < 16; t++) {
            int idx = tid + t * 256;
            int s   = idx >> 11;
            int rem = idx & 2047;
            int r   = rem >> 4;
            int kc  = rem & 15;
            const __nv_bfloat16* src = (s ? g_x1 : g_x0) + (j0 + r) * D + kc * 8;
            uint32_t dst = sb + OFF_B0 + s * 32768 + (kc >> 3) * 16384 + r * 128
                         + (((kc & 7) << 4) ^ ((r & 7) << 4));
            CP16(dst, src);
        }
        CP_COMMIT();
    }

    // ---- per-thread stats for 4 fixed rows ----
    float ps[4], pmax[4], ns[4], nmin[4], sqi[4];
    int tgi[4], rowg[4];
    #pragma unroll
    for (int q = 0; q < 4; q++) {
        rowg[q] = i0 + wr * 32 + q * 8 + (lane >> 2);
        float2 st = g_sqtg[rowg[q]];
        sqi[q] = st.x;
        tgi[q] = __float_as_int(st.y);
        ps[q] = 0.0f; ns[q] = 0.0f; pmax[q] = -FINF; nmin[q] = FINF;
    }

    CP_WAIT(0);
    __syncthreads();

    for (int c = 0; c < 32; c++) {
        int buf = c & 1;
        int j0  = jb + c * 128;

        // prefetch next chunk into other buffer
        if (c + 1 < 32) {
            int jn = jb + (c + 1) * 128;
            uint32_t bdst = sb + ((c + 1) & 1 ? OFF_B1 : OFF_B0);
            #pragma unroll
            for (int t = 0; t < 16; t++) {
                int idx = tid + t * 256;
                int s   = idx >> 11;
                int rem = idx & 2047;
                int r   = rem >> 4;
                int kc  = rem & 15;
                const __nv_bfloat16* src = (s ? g_x1 : g_x0) + (jn + r) * D + kc * 8;
                uint32_t dst = bdst + s * 32768 + (kc >> 3) * 16384 + r * 128
                             + (((kc & 7) << 4) ^ ((r & 7) << 4));
                CP16(dst, src);
            }
            CP_COMMIT();
            CP_WAIT(1);
        } else {
            CP_WAIT(0);
        }
        if (tid < 128) stage[tid] = g_sqtg[j0 + tid];
        __syncthreads();  // chunk c data + stage visible

        // ---- compute 128x128 (this warp: 32x64) with 3 bf16-split terms ----
        float acc[2][8][4];
        #pragma unroll
        for (int mi = 0; mi < 2; mi++)
            #pragma unroll
            for (int ni = 0; ni < 8; ni++)
                #pragma unroll
                for (int v = 0; v < 4; v++) acc[mi][ni][v] = 0.0f;

        uint32_t bbuf = sb + (buf ? OFF_B1 : OFF_B0);
        for (int t = 0; t < 3; t++) {
            uint32_t abase = sb + OFF_A + (t == 2 ? 32768 : 0);
            uint32_t bbase = bbuf + (t == 1 ? 32768 : 0);
            #pragma unroll
            for (int kk = 0; kk < 8; kk++) {
                uint32_t af[2][4];
                int kbA = kk * 32 + ((lane >> 4) << 4);
                int hA = kbA >> 7, wA = kbA & 127;
                #pragma unroll
                for (int mi = 0; mi < 2; mi++) {
                    int row = wr * 32 + mi * 16 + (lane & 15);
                    uint32_t ad = abase + hA * 16384 + row * 128
                                + (wA ^ ((row & 7) << 4));
                    LDSM4(af[mi], ad);
                }
                uint32_t bf[4][4];
                int kbB = kk * 32 + (((lane >> 3) & 1) << 4);
                int hB = kbB >> 7, wB = kbB & 127;
                #pragma unroll
                for (int g = 0; g < 4; g++) {
                    int col = wc * 64 + g * 16 + (lane & 7) + (((lane >> 4) & 1) << 3);
                    uint32_t bd = bbase + hB * 16384 + col * 128
                                + (wB ^ ((col & 7) << 4));
                    LDSM4(bf[g], bd);
                }
                #pragma unroll
                for (int mi = 0; mi < 2; mi++)
                    #pragma unroll
                    for (int g = 0; g < 4; g++) {
                        MMA(acc[mi][2 * g],     af[mi], bf[g][0], bf[g][1]);
                        MMA(acc[mi][2 * g + 1], af[mi], bf[g][2], bf[g][3]);
                    }
            }
        }

        // ---- epilogue: fold 32x64 distances into per-row stats ----
        #pragma unroll
        for (int mi = 0; mi < 2; mi++)
            #pragma unroll
            for (int ni = 0; ni < 8; ni++)
                #pragma unroll
                for (int v = 0; v < 4; v++) {
                    int slot = mi * 2 + (v >> 1);
                    int cl   = wc * 64 + ni * 8 + (lane & 3) * 2 + (v & 1);
                    float2 st = stage[cl];
                    int cg = j0 + cl;
                    float d2 = fmaxf(fmaf(-2.0f, acc[mi][ni][v], sqi[slot] + st.x),
                                     1e-12f);
                    bool same = (__float_as_int(st.y) == tgi[slot]);
                    if (same) {
                        if (cg != rowg[slot]) {
                            ps[slot] += d2;
                            pmax[slot] = fmaxf(pmax[slot], d2);
                        }
                    } else {
                        ns[slot] += d2;
                        nmin[slot] = fminf(nmin[slot], d2);
                    }
                }
        __syncthreads();  // done reading buf c + stage
    }

    // ---- reduce across the 4 lanes sharing each row, write partials ----
    #pragma unroll
    for (int q = 0; q < 4; q++) {
        float a = ps[q], b = pmax[q], cn = ns[q], d = nmin[q];
        #pragma unroll
        for (int o = 1; o <= 2; o <<= 1) {
            a  += __shfl_xor_sync(0xffffffffu, a, o);
            b   = fmaxf(b, __shfl_xor_sync(0xffffffffu, b, o));
            cn += __shfl_xor_sync(0xffffffffu, cn, o);
            d   = fminf(d, __shfl_xor_sync(0xffffffffu, d, o));
        }
        if ((lane & 3) == 0)
            g_part[(half * 2 + wc) * N + rowg[q]] = make_float4(a, b, cn, d);
    }
}

// ---------------------------------------------------------------------------
// Final: merge 4 partials, compute hinges, deterministic mean.
// ---------------------------------------------------------------------------
__global__ void final_kernel(float* __restrict__ out) {
    __shared__ float smr[256];
    float s = 0.0f;
    for (int row = threadIdx.x; row < N; row += 256) {
        float4 p0 = g_part[row];
        float4 p1 = g_part[N + row];
        float4 p2 = g_part[2 * N + row];
        float4 p3 = g_part[3 * N + row];
        float psum = p0.x + p1.x + p2.x + p3.x;
        float pmax = fmaxf(fmaxf(p0.y, p1.y), fmaxf(p2.y, p3.y));
        float nsum = p0.z + p1.z + p2.z + p3.z;
        float nmin = fminf(fminf(p0.w, p1.w), fminf(p2.w, p3.w));
        int tg = __float_as_int(g_sqtg[row].y);
        int cc = g_cc[tg];
        float sp = psum / (float)(cc - 1);
        float ap = pmax / sp + 0.5f * logf(sp);
        float sn = nsum / (float)(N - cc);
        float an = nmin / sn + 0.5f * logf(sn);
        s += fmaxf(ap - an + MARGIN, 0.0f);
    }
    smr[threadIdx.x] = s;
    __syncthreads();
    for (int o = 128; o > 0; o >>= 1) {
        if (threadIdx.x < o) smr[threadIdx.x] += smr[threadIdx.x + o];
        __syncthreads();
    }
    if (threadIdx.x == 0) out[0] = smr[0] / (float)N;
}

extern "C" void kernel_launch(void* const* d_in, const int* in_sizes, int n_in,
                              void* d_out, int out_size) {
    (void)in_sizes; (void)n_in; (void)out_size;
    const float* x   = (const float*)d_in[0];
    const void*  tgt = d_in[1];

    detect_kernel<<<1, 256>>>((const unsigned int*)tgt);
    prep_kernel<<<N, 128>>>(x, tgt);

    cudaFuncSetAttribute(main_kernel, cudaFuncAttributeMaxDynamicSharedMemorySize, SMEM_REQ);
    main_kernel<<<128, 256, SMEM_REQ>>>();

    final_kernel<<<1, 256>>>((float*)d_out);
}

// round 6
// speedup vs baseline: 3.9177x; 1.1042x over previous
#include <cuda_runtime.h>
#include <cuda_bf16.h>
#include <cstdint>

#define N 8192
#define D 128
#define MARGIN 0.3f
#define NCLS 256
#define FINF __int_as_float(0x7f800000)

__device__ __nv_bfloat16 g_x0[N * D];   // hi bf16 split
__device__ __nv_bfloat16 g_x1[N * D];   // lo bf16 split
__device__ float2        g_sqtg[N];     // (sq_norm, target-as-bits)
__device__ int           g_cc[NCLS];
__device__ int           g_is64;
__device__ float4        g_part[4 * N]; // per (half, wc) partial stats
__device__ float         g_bsum[32];

// ---------------- PTX helpers ----------------
__device__ __forceinline__ uint32_t smem_u32(const void* p) {
    uint32_t a;
    asm("{ .reg .u64 t; cvta.to.shared.u64 t, %1; cvt.u32.u64 %0, t; }"
        : "=r"(a) : "l"(p));
    return a;
}
#define CP16(dst, src) \
    asm volatile("cp.async.cg.shared.global [%0], [%1], 16;" \
        :: "r"(dst), "l"(src) : "memory")
#define CP_COMMIT() asm volatile("cp.async.commit_group;" ::: "memory")
#define CP_WAIT(n)  asm volatile("cp.async.wait_group %0;" :: "n"(n) : "memory")

#define LDSM4(r, a) \
    asm volatile("ldmatrix.sync.aligned.m8n8.x4.shared.b16 {%0,%1,%2,%3}, [%4];" \
        : "=r"((r)[0]), "=r"((r)[1]), "=r"((r)[2]), "=r"((r)[3]) : "r"(a))

#define MMA(c, a, b0_, b1_) \
    asm volatile("mma.sync.aligned.m16n8k16.row.col.f32.bf16.bf16.f32 " \
        "{%0,%1,%2,%3},{%4,%5,%6,%7},{%8,%9},{%0,%1,%2,%3};" \
        : "+f"((c)[0]), "+f"((c)[1]), "+f"((c)[2]), "+f"((c)[3]) \
        : "r"((a)[0]), "r"((a)[1]), "r"((a)[2]), "r"((a)[3]), "r"(b0_), "r"(b1_))

// SMEM layout (64KB A, 2x64KB B, 1KB stage)
#define OFF_A     0
#define OFF_B0    65536
#define OFF_B1    131072
#define OFF_STAGE 196608
#define SMEM_REQ  (196608 + 1024)

// ---------------------------------------------------------------------------
__global__ void detect_kernel(const unsigned int* __restrict__ t) {
    __shared__ unsigned int sred[256];
    unsigned int acc = 0;
    for (int i = threadIdx.x; i < N / 2; i += 256) acc |= t[2 * i + 1];
    sred[threadIdx.x] = acc;
    __syncthreads();
    for (int s = 128; s > 0; s >>= 1) {
        if (threadIdx.x < s) sred[threadIdx.x] |= sred[threadIdx.x + s];
        __syncthreads();
    }
    if (threadIdx.x == 0) g_is64 = (sred[0] == 0u) ? 1 : 0;
    if (threadIdx.x < NCLS) g_cc[threadIdx.x] = 0;
}

// bf16 split + norms + targets + class histogram.
// Grid 128 x 256 threads: each warp owns 8 rows; lane holds one float4/row.
__global__ void prep_kernel(const float* __restrict__ x, const void* __restrict__ tgt) {
    int lane = threadIdx.x & 31;
    int gw   = (blockIdx.x * 8) + (threadIdx.x >> 5);  // 0..1023
    const float4* X4 = (const float4*)x;
    uint2* O0 = (uint2*)g_x0;
    uint2* O1 = (uint2*)g_x1;
    int is64 = g_is64;

    #pragma unroll
    for (int r = 0; r < 8; r++) {
        int row = gw * 8 + r;
        float4 v = X4[row * 32 + lane];

        __nv_bfloat16 h0 = __float2bfloat16(v.x);
        __nv_bfloat16 h1 = __float2bfloat16(v.y);
        __nv_bfloat16 h2 = __float2bfloat16(v.z);
        __nv_bfloat16 h3 = __float2bfloat16(v.w);
        __nv_bfloat162 p01 = __halves2bfloat162(h0, h1);
        __nv_bfloat162 p23 = __halves2bfloat162(h2, h3);
        O0[row * 32 + lane] = make_uint2(*(uint32_t*)&p01, *(uint32_t*)&p23);

        __nv_bfloat162 q01 = __halves2bfloat162(
            __float2bfloat16(v.x - __bfloat162float(h0)),
            __float2bfloat16(v.y - __bfloat162float(h1)));
        __nv_bfloat162 q23 = __halves2bfloat162(
            __float2bfloat16(v.z - __bfloat162float(h2)),
            __float2bfloat16(v.w - __bfloat162float(h3)));
        O1[row * 32 + lane] = make_uint2(*(uint32_t*)&q01, *(uint32_t*)&q23);

        float s = v.x * v.x + v.y * v.y + v.z * v.z + v.w * v.w;
        #pragma unroll
        for (int o = 16; o > 0; o >>= 1) s += __shfl_xor_sync(0xffffffffu, s, o);
        if (lane == 0) {
            int tg;
            if (is64) tg = (int)((const long long*)tgt)[row];
            else      tg = ((const int*)tgt)[row];
            g_sqtg[row] = make_float2(s, __int_as_float(tg));
            atomicAdd(&g_cc[tg], 1);
        }
    }
}

// ---------------------------------------------------------------------------
// Main: mma.sync bf16-split distance GEMM + fused per-row stats.
// (unchanged from R5 — measured near HMMA issue floor)
// ---------------------------------------------------------------------------
__global__ void __launch_bounds__(256, 1) main_kernel() {
    extern __shared__ __align__(1024) char smraw[];
    uint32_t sb = smem_u32(smraw);
    float2* stage = (float2*)(smraw + OFF_STAGE);

    int tid  = threadIdx.x;
    int lane = tid & 31;
    int wid  = tid >> 5;
    int wr   = wid >> 1;          // row group (32 rows)
    int wc   = wid & 1;           // col group (64 cols)
    int i0   = (blockIdx.x >> 1) * 128;
    int half = blockIdx.x & 1;
    int jb   = half * 4096;

    // ---- A tile via cp.async (rows i0..i0+127, both splits) ----
    #pragma unroll
    for (int t = 0; t < 16; t++) {
        int idx = tid + t * 256;           // 0..4095 16B chunks
        int s   = idx >> 11;
        int rem = idx & 2047;
        int r   = rem >> 4;
        int kc  = rem & 15;
        const __nv_bfloat16* src = (s ? g_x1 : g_x0) + (i0 + r) * D + kc * 8;
        uint32_t dst = sb + OFF_A + s * 32768 + (kc >> 3) * 16384 + r * 128
                     + (((kc & 7) << 4) ^ ((r & 7) << 4));
        CP16(dst, src);
    }
    CP_COMMIT();

    // ---- B chunk 0 ----
    {
        int j0 = jb;
        #pragma unroll
        for (int t = 0; t < 16; t++) {
            int idx = tid + t * 256;
            int s   = idx >> 11;
            int rem = idx & 2047;
            int r   = rem >> 4;
            int kc  = rem & 15;
            const __nv_bfloat16* src = (s ? g_x1 : g_x0) + (j0 + r) * D + kc * 8;
            uint32_t dst = sb + OFF_B0 + s * 32768 + (kc >> 3) * 16384 + r * 128
                         + (((kc & 7) << 4) ^ ((r & 7) << 4));
            CP16(dst, src);
        }
        CP_COMMIT();
    }

    // ---- per-thread stats for 4 fixed rows ----
    float ps[4], pmax[4], ns[4], nmin[4], sqi[4];
    int tgi[4], rowg[4];
    #pragma unroll
    for (int q = 0; q < 4; q++) {
        rowg[q] = i0 + wr * 32 + q * 8 + (lane >> 2);
        float2 st = g_sqtg[rowg[q]];
        sqi[q] = st.x;
        tgi[q] = __float_as_int(st.y);
        ps[q] = 0.0f; ns[q] = 0.0f; pmax[q] = -FINF; nmin[q] = FINF;
    }

    CP_WAIT(0);
    __syncthreads();

    for (int c = 0; c < 32; c++) {
        int buf = c & 1;
        int j0  = jb + c * 128;

        // prefetch next chunk into other buffer
        if (c + 1 < 32) {
            int jn = jb + (c + 1) * 128;
            uint32_t bdst = sb + ((c + 1) & 1 ? OFF_B1 : OFF_B0);
            #pragma unroll
            for (int t = 0; t < 16; t++) {
                int idx = tid + t * 256;
                int s   = idx >> 11;
                int rem = idx & 2047;
                int r   = rem >> 4;
                int kc  = rem & 15;
                const __nv_bfloat16* src = (s ? g_x1 : g_x0) + (jn + r) * D + kc * 8;
                uint32_t dst = bdst + s * 32768 + (kc >> 3) * 16384 + r * 128
                             + (((kc & 7) << 4) ^ ((r & 7) << 4));
                CP16(dst, src);
            }
            CP_COMMIT();
            CP_WAIT(1);
        } else {
            CP_WAIT(0);
        }
        if (tid < 128) stage[tid] = g_sqtg[j0 + tid];
        __syncthreads();  // chunk c data + stage visible

        // ---- compute 128x128 (this warp: 32x64) with 3 bf16-split terms ----
        float acc[2][8][4];
        #pragma unroll
        for (int mi = 0; mi < 2; mi++)
            #pragma unroll
            for (int ni = 0; ni < 8; ni++)
                #pragma unroll
                for (int v = 0; v < 4; v++) acc[mi][ni][v] = 0.0f;

        uint32_t bbuf = sb + (buf ? OFF_B1 : OFF_B0);
        for (int t = 0; t < 3; t++) {
            uint32_t abase = sb + OFF_A + (t == 2 ? 32768 : 0);
            uint32_t bbase = bbuf + (t == 1 ? 32768 : 0);
            #pragma unroll
            for (int kk = 0; kk < 8; kk++) {
                uint32_t af[2][4];
                int kbA = kk * 32 + ((lane >> 4) << 4);
                int hA = kbA >> 7, wA = kbA & 127;
                #pragma unroll
                for (int mi = 0; mi < 2; mi++) {
                    int row = wr * 32 + mi * 16 + (lane & 15);
                    uint32_t ad = abase + hA * 16384 + row * 128
                                + (wA ^ ((row & 7) << 4));
                    LDSM4(af[mi], ad);
                }
                uint32_t bf[4][4];
                int kbB = kk * 32 + (((lane >> 3) & 1) << 4);
                int hB = kbB >> 7, wB = kbB & 127;
                #pragma unroll
                for (int g = 0; g < 4; g++) {
                    int col = wc * 64 + g * 16 + (lane & 7) + (((lane >> 4) & 1) << 3);
                    uint32_t bd = bbase + hB * 16384 + col * 128
                                + (wB ^ ((col & 7) << 4));
                    LDSM4(bf[g], bd);
                }
                #pragma unroll
                for (int mi = 0; mi < 2; mi++)
                    #pragma unroll
                    for (int g = 0; g < 4; g++) {
                        MMA(acc[mi][2 * g],     af[mi], bf[g][0], bf[g][1]);
                        MMA(acc[mi][2 * g + 1], af[mi], bf[g][2], bf[g][3]);
                    }
            }
        }

        // ---- epilogue: fold 32x64 distances into per-row stats ----
        #pragma unroll
        for (int mi = 0; mi < 2; mi++)
            #pragma unroll
            for (int ni = 0; ni < 8; ni++)
                #pragma unroll
                for (int v = 0; v < 4; v++) {
                    int slot = mi * 2 + (v >> 1);
                    int cl   = wc * 64 + ni * 8 + (lane & 3) * 2 + (v & 1);
                    float2 st = stage[cl];
                    int cg = j0 + cl;
                    float d2 = fmaxf(fmaf(-2.0f, acc[mi][ni][v], sqi[slot] + st.x),
                                     1e-12f);
                    bool same = (__float_as_int(st.y) == tgi[slot]);
                    if (same) {
                        if (cg != rowg[slot]) {
                            ps[slot] += d2;
                            pmax[slot] = fmaxf(pmax[slot], d2);
                        }
                    } else {
                        ns[slot] += d2;
                        nmin[slot] = fminf(nmin[slot], d2);
                    }
                }
        __syncthreads();  // done reading buf c + stage
    }

    // ---- reduce across the 4 lanes sharing each row, write partials ----
    #pragma unroll
    for (int q = 0; q < 4; q++) {
        float a = ps[q], b = pmax[q], cn = ns[q], d = nmin[q];
        #pragma unroll
        for (int o = 1; o <= 2; o <<= 1) {
            a  += __shfl_xor_sync(0xffffffffu, a, o);
            b   = fmaxf(b, __shfl_xor_sync(0xffffffffu, b, o));
            cn += __shfl_xor_sync(0xffffffffu, cn, o);
            d   = fminf(d, __shfl_xor_sync(0xffffffffu, d, o));
        }
        if ((lane & 3) == 0)
            g_part[(half * 2 + wc) * N + rowg[q]] = make_float4(a, b, cn, d);
    }
}

// ---------------------------------------------------------------------------
// Hinge per row (parallel), block partial sums.
// ---------------------------------------------------------------------------
__global__ void hinge_kernel() {
    __shared__ float smr[256];
    int row = blockIdx.x * 256 + threadIdx.x;
    float4 p0 = g_part[row];
    float4 p1 = g_part[N + row];
    float4 p2 = g_part[2 * N + row];
    float4 p3 = g_part[3 * N + row];
    float psum = p0.x + p1.x + p2.x + p3.x;
    float pmax = fmaxf(fmaxf(p0.y, p1.y), fmaxf(p2.y, p3.y));
    float nsum = p0.z + p1.z + p2.z + p3.z;
    float nmin = fminf(fminf(p0.w, p1.w), fminf(p2.w, p3.w));
    int tg = __float_as_int(g_sqtg[row].y);
    int cc = g_cc[tg];
    float sp = psum / (float)(cc - 1);
    float ap = pmax / sp + 0.5f * logf(sp);
    float sn = nsum / (float)(N - cc);
    float an = nmin / sn + 0.5f * logf(sn);
    float h = fmaxf(ap - an + MARGIN, 0.0f);

    smr[threadIdx.x] = h;
    __syncthreads();
    for (int o = 128; o > 0; o >>= 1) {
        if (threadIdx.x < o) smr[threadIdx.x] += smr[threadIdx.x + o];
        __syncthreads();
    }
    if (threadIdx.x == 0) g_bsum[blockIdx.x] = smr[0];
}

__global__ void sum_kernel(float* __restrict__ out) {
    float v = g_bsum[threadIdx.x];
    #pragma unroll
    for (int o = 16; o > 0; o >>= 1) v += __shfl_xor_sync(0xffffffffu, v, o);
    if (threadIdx.x == 0) out[0] = v / (float)N;
}

extern "C" void kernel_launch(void* const* d_in, const int* in_sizes, int n_in,
                              void* d_out, int out_size) {
    (void)in_sizes; (void)n_in; (void)out_size;
    const float* x   = (const float*)d_in[0];
    const void*  tgt = d_in[1];

    detect_kernel<<<1, 256>>>((const unsigned int*)tgt);
    prep_kernel<<<128, 256>>>(x, tgt);

    cudaFuncSetAttribute(main_kernel, cudaFuncAttributeMaxDynamicSharedMemorySize, SMEM_REQ);
    main_kernel<<<128, 256, SMEM_REQ>>>();

    hinge_kernel<<<32, 256>>>();
    sum_kernel<<<1, 32>>>((float*)d_out);
}